// round 4
// baseline (speedup 1.0000x reference)
#include <cuda_runtime.h>

#define CHUNKS 8
#define ROWS_PER 16
#define NBLK (256 * CHUNKS)   // 2048
#define NTHR 160               // 5 warps

__device__ float g_part[NBLK][4];
__device__ unsigned int g_ctr;

// 1st+2nd derivative, torch.gradient semantics on a cropped 126-array.
// cls: 0=left edge, 1=left+1, 2=interior, 3=right-1, 4=right edge
__device__ __forceinline__ void d12(float fm2, float fm1, float f0, float fp1, float fp2,
                                    int cls, float inv_h, float inv_2h, float c2,
                                    float& d1, float& d2) {
    if (cls == 2)      { d1 = (fp1 - fm1) * inv_2h; d2 = (fp2 - 2.f * f0 + fm2) * c2; }
    else if (cls == 0) { d1 = (fp1 - f0) * inv_h;
                         d2 = ((fp2 - f0) * inv_2h - (fp1 - f0) * inv_h) * inv_h; }
    else if (cls == 1) { d1 = (fp1 - fm1) * inv_2h;
                         d2 = ((fp2 - f0) * inv_2h - (f0 - fm1) * inv_h) * inv_2h; }
    else if (cls == 3) { d1 = (fp1 - fm1) * inv_2h;
                         d2 = ((fp1 - f0) * inv_h - (f0 - fm2) * inv_2h) * inv_2h; }
    else               { d1 = (f0 - fm1) * inv_h;
                         d2 = ((f0 - fm1) * inv_h - (f0 - fm2) * inv_2h) * inv_h; }
}

__global__ __launch_bounds__(NTHR) void physics_kernel(
    const float* __restrict__ inp,   // (256,1,128,128)
    const float* __restrict__ outp,  // (256,3,128,128)
    const float* __restrict__ tgt,   // (256,3,128,128)
    float* __restrict__ out)
{
    const int blk   = blockIdx.x;
    const int b     = blk >> 3;
    const int chunk = blk & 7;
    const int tx    = threadIdx.x;
    const int y0    = chunk * ROWS_PER;

    constexpr float INV_SX  = 127.0f / 1.2f;
    constexpr float INV_2SX = 127.0f / 2.4f;
    constexpr float INV_SY  = 127.0f / 0.8f;
    constexpr float INV_2SY = 127.0f / 1.6f;
    constexpr float C2X = INV_2SX * INV_2SX;
    constexpr float C2Y = INV_2SY * INV_2SY;

    const float* Ob = outp + b * 49152;
    const float* Tb = tgt  + b * 49152;
    const float* Ib = inp  + b * 16384;

    float s_base = 0.f, s_bc = 0.f, s_cont = 0.f, s_ns = 0.f;

    // ---------------- base loss + boundary loss (float4 over 16 rows) ----------------
    {
        const float4* O4 = (const float4*)Ob;
        const float4* T4 = (const float4*)Tb;
#pragma unroll
        for (int it = 0; it < 4; ++it) {
            int idx4 = tx + it * NTHR;           // 0..639, need <512
            if (idx4 < 512) {
                int y    = y0 + (idx4 >> 5);
                int col4 = idx4 & 31;
                int idx  = y * 32 + col4;
                float4 o0 = O4[idx], o1 = O4[4096 + idx], o2 = O4[8192 + idx];
                float4 t0 = T4[idx], t1 = T4[4096 + idx], t2 = T4[8192 + idx];
                float d;
                d = o0.x - t0.x; s_base += d * d;  d = o0.y - t0.y; s_base += d * d;
                d = o0.z - t0.z; s_base += d * d;  d = o0.w - t0.w; s_base += d * d;
                d = o1.x - t1.x; s_base += d * d;  d = o1.y - t1.y; s_base += d * d;
                d = o1.z - t1.z; s_base += d * d;  d = o1.w - t1.w; s_base += d * d;
                d = o2.x - t2.x; s_base += d * d;  d = o2.y - t2.y; s_base += d * d;
                d = o2.z - t2.z; s_base += d * d;  d = o2.w - t2.w; s_base += d * d;

                bool midrow = (y >= 55) && (y < 73);
                if (y == 0 || y == 127)
                    s_bc += o1.x * o1.x + o1.y * o1.y + o1.z * o1.z + o1.w * o1.w
                          + o2.x * o2.x + o2.y * o2.y + o2.z * o2.z + o2.w * o2.w;
                if (col4 == 0) {
                    if (midrow) { float e = o1.x - 0.01f; s_bc += e * e; }
                    else        s_bc += o1.x * o1.x + o2.x * o2.x;
                }
                if (col4 == 31) {
                    if (midrow) s_bc += o0.w * o0.w;
                    else        s_bc += o1.w * o1.w + o2.w * o2.w;
                }
            }
        }
    }

    // ---------------- PDE on cropped 126x126 interior (barrier-free) ----------------
    // Cropped coords (j,c) map to global (j+1, c+1).
    // Warp w, lane l: loads column cl = clamp(w*28 + l - 2), computes c = w*28+l-2
    // for lanes 2..29 with c < 126. x-neighbors come from warp shuffles.
    const int lane = tx & 31;
    const int w    = tx >> 5;
    const int c    = w * 28 + lane - 2;            // compute column (may be out of range)
    const int cl   = min(max(c, 0), 125);          // load column (clamped)
    const bool active = (lane >= 2) && (lane <= 29) && (c < 126);
    const int cls_x = (c <= 0) ? 0 : (c == 1 ? 1 : (c >= 125 ? 4 : (c == 124 ? 3 : 2)));

    const float* U = Ob + 16384 + 129 + cl;
    const float* V = Ob + 32768 + 129 + cl;
    const float* P = Ob + 129 + cl;
    const float* A = Ib + 129 + cl;

    const int jlo = max(y0 - 1, 0);
    const int jhi = min(y0 + ROWS_PER - 1, 126);

    // register y-windows
    float u_m2 = 0.f, u_m1 = 0.f, u_c, u_p1, u_p2;
    float v_m2 = 0.f, v_m1 = 0.f, v_c, v_p1, v_p2;
    float p_m1 = 0.f, p_c, p_p1;

    if (jlo >= 2) { u_m2 = U[(jlo - 2) * 128]; v_m2 = V[(jlo - 2) * 128]; }
    if (jlo >= 1) { u_m1 = U[(jlo - 1) * 128]; v_m1 = V[(jlo - 1) * 128];
                    p_m1 = P[(jlo - 1) * 128]; }
    u_c  = U[jlo * 128];        v_c  = V[jlo * 128];        p_c  = P[jlo * 128];
    u_p1 = U[(jlo + 1) * 128];  v_p1 = V[(jlo + 1) * 128];  p_p1 = P[(jlo + 1) * 128];
    u_p2 = U[(jlo + 2) * 128];  v_p2 = V[(jlo + 2) * 128];

    for (int j = jlo; j < jhi; ++j) {
        // prefetch next rows (block-uniform predicates -> warp stays converged)
        float nu = 0.f, nv = 0.f, np = 0.f;
        if (j + 3 <= 125) { nu = U[(j + 3) * 128]; nv = V[(j + 3) * 128]; }
        if (j + 2 <= 125) { np = P[(j + 2) * 128]; }
        float alpha = A[j * 128];

        // x-neighbors via warp shuffle (all 32 lanes participate)
        float uxm2 = __shfl_up_sync(0xffffffffu, u_c, 2);
        float uxm1 = __shfl_up_sync(0xffffffffu, u_c, 1);
        float uxp1 = __shfl_down_sync(0xffffffffu, u_c, 1);
        float uxp2 = __shfl_down_sync(0xffffffffu, u_c, 2);
        float vxm2 = __shfl_up_sync(0xffffffffu, v_c, 2);
        float vxm1 = __shfl_up_sync(0xffffffffu, v_c, 1);
        float vxp1 = __shfl_down_sync(0xffffffffu, v_c, 1);
        float vxp2 = __shfl_down_sync(0xffffffffu, v_c, 2);
        float pxm1 = __shfl_up_sync(0xffffffffu, p_c, 1);
        float pxp1 = __shfl_down_sync(0xffffffffu, p_c, 1);

        if (active) {
            float du_dx, du_dxx, dv_dx, dv_dxx;
            d12(uxm2, uxm1, u_c, uxp1, uxp2, cls_x, INV_SX, INV_2SX, C2X, du_dx, du_dxx);
            d12(vxm2, vxm1, v_c, vxp1, vxp2, cls_x, INV_SX, INV_2SX, C2X, dv_dx, dv_dxx);

            float dp_dx = (c == 0)   ? (pxp1 - p_c) * INV_SX
                        : (c == 125) ? (p_c - pxm1) * INV_SX
                                     : (pxp1 - pxm1) * INV_2SX;

            int cls_y = (j >= 2 && j <= 123) ? 2 : (j == 0 ? 0 : (j == 1 ? 1 : (j == 124 ? 3 : 4)));
            float du_dy, du_dyy, dv_dy, dv_dyy;
            d12(u_m2, u_m1, u_c, u_p1, u_p2, cls_y, INV_SY, INV_2SY, C2Y, du_dy, du_dyy);
            d12(v_m2, v_m1, v_c, v_p1, v_p2, cls_y, INV_SY, INV_2SY, C2Y, dv_dy, dv_dyy);

            float dp_dy = (j == 0)   ? (p_p1 - p_c) * INV_SY
                        : (j == 125) ? (p_c - p_m1) * INV_SY
                                     : (p_p1 - p_m1) * INV_2SY;

            float div = du_dx + dv_dy;
            s_cont += div * div;
            float xres = u_c * du_dx + v_c * du_dy + dp_dx - (du_dxx + du_dyy) + alpha * u_c;
            float yres = u_c * dv_dx + v_c * dv_dy + dp_dy - (dv_dxx + dv_dyy) + alpha * v_c;
            s_ns += xres * xres + yres * yres;
        }

        // rotate register windows
        u_m2 = u_m1; u_m1 = u_c; u_c = u_p1; u_p1 = u_p2; u_p2 = nu;
        v_m2 = v_m1; v_m1 = v_c; v_c = v_p1; v_p1 = v_p2; v_p2 = nv;
        p_m1 = p_c;  p_c = p_p1; p_p1 = np;
    }

    // ---------------- block reduction -> g_part ----------------
    {
        float vals[4] = {s_base, s_bc, s_cont, s_ns};
        __shared__ float rbuf[4][5];
#pragma unroll
        for (int k = 0; k < 4; ++k) {
            float v = vals[k];
#pragma unroll
            for (int off = 16; off; off >>= 1) v += __shfl_down_sync(0xffffffffu, v, off);
            if (lane == 0) rbuf[k][w] = v;
        }
        __syncthreads();
        if (tx == 0) {
#pragma unroll
            for (int k = 0; k < 4; ++k)
                g_part[blk][k] = rbuf[k][0] + rbuf[k][1] + rbuf[k][2] + rbuf[k][3] + rbuf[k][4];
        }
    }

    // ---------------- fused finalize: last block reduces all partials ----------------
    __shared__ int isLast;
    if (tx == 0) {
        __threadfence();
        unsigned t = atomicAdd(&g_ctr, 1u);
        isLast = (t == (unsigned)(NBLK - 1)) ? 1 : 0;
    }
    __syncthreads();

    if (isLast) {
        double a0 = 0.0, a1 = 0.0, a2 = 0.0, a3 = 0.0;
        const float4* gp = (const float4*)g_part;
        for (int idx = tx; idx < NBLK; idx += NTHR) {
            float4 v = __ldcg(&gp[idx]);
            a0 += (double)v.x; a1 += (double)v.y; a2 += (double)v.z; a3 += (double)v.w;
        }
#pragma unroll
        for (int off = 16; off; off >>= 1) {
            a0 += __shfl_down_sync(0xffffffffu, a0, off);
            a1 += __shfl_down_sync(0xffffffffu, a1, off);
            a2 += __shfl_down_sync(0xffffffffu, a2, off);
            a3 += __shfl_down_sync(0xffffffffu, a3, off);
        }
        __shared__ double sd[4][5];
        if (lane == 0) { sd[0][w] = a0; sd[1][w] = a1; sd[2][w] = a2; sd[3][w] = a3; }
        __syncthreads();
        if (tx == 0) {
            double t0 = 0, t1 = 0, t2 = 0, t3 = 0;
#pragma unroll
            for (int k = 0; k < 5; ++k) { t0 += sd[0][k]; t1 += sd[1][k]; t2 += sd[2][k]; t3 += sd[3][k]; }
            const double NI = 256.0 * 126.0 * 126.0;
            double loss_base = t0 / 300000.0;
            double loss_bc   = t1 / (256.0 * 988.0);
            double loss_cont = (t2 / NI) / 1e-5;
            double loss_ns   = (t3 / (NI * 2.0)) / 0.01;
            double A_LOSS = 1.0 - 0.3 - 0.3 - 0.3;
            out[0] = (float)(A_LOSS * loss_base + 0.3 * loss_cont + 0.3 * loss_ns + 0.3 * loss_bc);
            g_ctr = 0u;   // reset for graph replay
        }
    }
}

extern "C" void kernel_launch(void* const* d_in, const int* in_sizes, int n_in,
                              void* d_out, int out_size) {
    const int SMALL = 256 * 128 * 128;
    int idx_in = 0;
    for (int i = 0; i < n_in; ++i)
        if (in_sizes[i] == SMALL) { idx_in = i; break; }
    const float* inp = (const float*)d_in[idx_in];
    const float* big[2];
    int nb = 0;
    for (int i = 0; i < n_in && nb < 2; ++i)
        if (i != idx_in) big[nb++] = (const float*)d_in[i];
    const float* outp = big[0];
    const float* tgt  = big[1];

    physics_kernel<<<NBLK, NTHR>>>(inp, outp, tgt, (float*)d_out);
}

// round 5
// speedup vs baseline: 1.0455x; 1.0455x over previous
#include <cuda_runtime.h>

#define CHUNKS 4
#define ROWS_PER 32
#define NBLK (256 * CHUNKS)   // 1024 -> single wave on 148 SMs
#define NTHR 160               // 5 warps

__device__ float g_part[NBLK][4];
__device__ unsigned int g_ctr;

// 1st+2nd derivative, torch.gradient semantics on a cropped 126-array.
// cls: 0=left edge, 1=left+1, 2=interior, 3=right-1, 4=right edge
__device__ __forceinline__ void d12(float fm2, float fm1, float f0, float fp1, float fp2,
                                    int cls, float inv_h, float inv_2h, float c2,
                                    float& d1, float& d2) {
    if (cls == 2)      { d1 = (fp1 - fm1) * inv_2h; d2 = (fp2 - 2.f * f0 + fm2) * c2; }
    else if (cls == 0) { d1 = (fp1 - f0) * inv_h;
                         d2 = ((fp2 - f0) * inv_2h - (fp1 - f0) * inv_h) * inv_h; }
    else if (cls == 1) { d1 = (fp1 - fm1) * inv_2h;
                         d2 = ((fp2 - f0) * inv_2h - (f0 - fm1) * inv_h) * inv_2h; }
    else if (cls == 3) { d1 = (fp1 - fm1) * inv_2h;
                         d2 = ((fp1 - f0) * inv_h - (f0 - fm2) * inv_2h) * inv_2h; }
    else               { d1 = (f0 - fm1) * inv_h;
                         d2 = ((f0 - fm1) * inv_h - (f0 - fm2) * inv_2h) * inv_h; }
}

__global__ __launch_bounds__(NTHR) void physics_kernel(
    const float* __restrict__ inp,   // (256,1,128,128)
    const float* __restrict__ outp,  // (256,3,128,128)
    const float* __restrict__ tgt,   // (256,3,128,128)
    float* __restrict__ out)
{
    const int blk   = blockIdx.x;
    const int b     = blk >> 2;
    const int chunk = blk & 3;
    const int tx    = threadIdx.x;
    const int y0    = chunk * ROWS_PER;

    constexpr float INV_SX  = 127.0f / 1.2f;
    constexpr float INV_2SX = 127.0f / 2.4f;
    constexpr float INV_SY  = 127.0f / 0.8f;
    constexpr float INV_2SY = 127.0f / 1.6f;
    constexpr float C2X = INV_2SX * INV_2SX;
    constexpr float C2Y = INV_2SY * INV_2SY;

    const float* Ob = outp + b * 49152;
    const float* Tb = tgt  + b * 49152;
    const float* Ib = inp  + b * 16384;

    float s_base = 0.f, s_bc = 0.f, s_cont = 0.f, s_ns = 0.f;

    // ---------------- base loss + boundary loss (float4 over 32 rows) ----------------
    {
        const float4* O4 = (const float4*)Ob;
        const float4* T4 = (const float4*)Tb;
#pragma unroll
        for (int it = 0; it < 7; ++it) {
            int idx4 = tx + it * NTHR;           // 0..1119, need <1024
            if (idx4 < 1024) {
                int y    = y0 + (idx4 >> 5);
                int col4 = idx4 & 31;
                int idx  = y * 32 + col4;
                float4 o0 = O4[idx], o1 = O4[4096 + idx], o2 = O4[8192 + idx];
                float4 t0 = T4[idx], t1 = T4[4096 + idx], t2 = T4[8192 + idx];
                float d;
                d = o0.x - t0.x; s_base += d * d;  d = o0.y - t0.y; s_base += d * d;
                d = o0.z - t0.z; s_base += d * d;  d = o0.w - t0.w; s_base += d * d;
                d = o1.x - t1.x; s_base += d * d;  d = o1.y - t1.y; s_base += d * d;
                d = o1.z - t1.z; s_base += d * d;  d = o1.w - t1.w; s_base += d * d;
                d = o2.x - t2.x; s_base += d * d;  d = o2.y - t2.y; s_base += d * d;
                d = o2.z - t2.z; s_base += d * d;  d = o2.w - t2.w; s_base += d * d;

                bool midrow = (y >= 55) && (y < 73);
                if (y == 0 || y == 127)
                    s_bc += o1.x * o1.x + o1.y * o1.y + o1.z * o1.z + o1.w * o1.w
                          + o2.x * o2.x + o2.y * o2.y + o2.z * o2.z + o2.w * o2.w;
                if (col4 == 0) {
                    if (midrow) { float e = o1.x - 0.01f; s_bc += e * e; }
                    else        s_bc += o1.x * o1.x + o2.x * o2.x;
                }
                if (col4 == 31) {
                    if (midrow) s_bc += o0.w * o0.w;
                    else        s_bc += o1.w * o1.w + o2.w * o2.w;
                }
            }
        }
    }

    // ---------------- PDE on cropped 126x126 interior (barrier-free) ----------------
    // Cropped coords (j,c) map to global (j+1, c+1).
    // Warp w, lane l: loads column cl = clamp(w*28 + l - 2), computes c = w*28+l-2
    // for lanes 2..29 with c < 126. x-neighbors come from warp shuffles.
    const int lane = tx & 31;
    const int w    = tx >> 5;
    const int c    = w * 28 + lane - 2;            // compute column (may be out of range)
    const int cl   = min(max(c, 0), 125);          // load column (clamped)
    const bool active = (lane >= 2) && (lane <= 29) && (c < 126);
    const int cls_x = (c <= 0) ? 0 : (c == 1 ? 1 : (c >= 125 ? 4 : (c == 124 ? 3 : 2)));

    const float* U = Ob + 16384 + 129 + cl;
    const float* V = Ob + 32768 + 129 + cl;
    const float* P = Ob + 129 + cl;
    const float* A = Ib + 129 + cl;

    const int jlo = max(y0 - 1, 0);
    const int jhi = min(y0 + ROWS_PER - 1, 126);

    // register y-windows
    float u_m2 = 0.f, u_m1 = 0.f, u_c, u_p1, u_p2;
    float v_m2 = 0.f, v_m1 = 0.f, v_c, v_p1, v_p2;
    float p_m1 = 0.f, p_c, p_p1;

    if (jlo >= 2) { u_m2 = U[(jlo - 2) * 128]; v_m2 = V[(jlo - 2) * 128]; }
    if (jlo >= 1) { u_m1 = U[(jlo - 1) * 128]; v_m1 = V[(jlo - 1) * 128];
                    p_m1 = P[(jlo - 1) * 128]; }
    u_c  = U[jlo * 128];        v_c  = V[jlo * 128];        p_c  = P[jlo * 128];
    u_p1 = U[(jlo + 1) * 128];  v_p1 = V[(jlo + 1) * 128];  p_p1 = P[(jlo + 1) * 128];
    u_p2 = U[(jlo + 2) * 128];  v_p2 = V[(jlo + 2) * 128];

    for (int j = jlo; j < jhi; ++j) {
        // prefetch next rows (block-uniform predicates -> warp stays converged)
        float nu = 0.f, nv = 0.f, np = 0.f;
        if (j + 3 <= 125) { nu = U[(j + 3) * 128]; nv = V[(j + 3) * 128]; }
        if (j + 2 <= 125) { np = P[(j + 2) * 128]; }
        float alpha = A[j * 128];

        // x-neighbors via warp shuffle (all 32 lanes participate)
        float uxm2 = __shfl_up_sync(0xffffffffu, u_c, 2);
        float uxm1 = __shfl_up_sync(0xffffffffu, u_c, 1);
        float uxp1 = __shfl_down_sync(0xffffffffu, u_c, 1);
        float uxp2 = __shfl_down_sync(0xffffffffu, u_c, 2);
        float vxm2 = __shfl_up_sync(0xffffffffu, v_c, 2);
        float vxm1 = __shfl_up_sync(0xffffffffu, v_c, 1);
        float vxp1 = __shfl_down_sync(0xffffffffu, v_c, 1);
        float vxp2 = __shfl_down_sync(0xffffffffu, v_c, 2);
        float pxm1 = __shfl_up_sync(0xffffffffu, p_c, 1);
        float pxp1 = __shfl_down_sync(0xffffffffu, p_c, 1);

        if (active) {
            float du_dx, du_dxx, dv_dx, dv_dxx;
            d12(uxm2, uxm1, u_c, uxp1, uxp2, cls_x, INV_SX, INV_2SX, C2X, du_dx, du_dxx);
            d12(vxm2, vxm1, v_c, vxp1, vxp2, cls_x, INV_SX, INV_2SX, C2X, dv_dx, dv_dxx);

            float dp_dx = (c == 0)   ? (pxp1 - p_c) * INV_SX
                        : (c == 125) ? (p_c - pxm1) * INV_SX
                                     : (pxp1 - pxm1) * INV_2SX;

            int cls_y = (j >= 2 && j <= 123) ? 2 : (j == 0 ? 0 : (j == 1 ? 1 : (j == 124 ? 3 : 4)));
            float du_dy, du_dyy, dv_dy, dv_dyy;
            d12(u_m2, u_m1, u_c, u_p1, u_p2, cls_y, INV_SY, INV_2SY, C2Y, du_dy, du_dyy);
            d12(v_m2, v_m1, v_c, v_p1, v_p2, cls_y, INV_SY, INV_2SY, C2Y, dv_dy, dv_dyy);

            float dp_dy = (j == 0)   ? (p_p1 - p_c) * INV_SY
                        : (j == 125) ? (p_c - p_m1) * INV_SY
                                     : (p_p1 - p_m1) * INV_2SY;

            float div = du_dx + dv_dy;
            s_cont += div * div;
            float xres = u_c * du_dx + v_c * du_dy + dp_dx - (du_dxx + du_dyy) + alpha * u_c;
            float yres = u_c * dv_dx + v_c * dv_dy + dp_dy - (dv_dxx + dv_dyy) + alpha * v_c;
            s_ns += xres * xres + yres * yres;
        }

        // rotate register windows
        u_m2 = u_m1; u_m1 = u_c; u_c = u_p1; u_p1 = u_p2; u_p2 = nu;
        v_m2 = v_m1; v_m1 = v_c; v_c = v_p1; v_p1 = v_p2; v_p2 = nv;
        p_m1 = p_c;  p_c = p_p1; p_p1 = np;
    }

    // ---------------- block reduction -> g_part ----------------
    {
        float vals[4] = {s_base, s_bc, s_cont, s_ns};
        __shared__ float rbuf[4][5];
#pragma unroll
        for (int k = 0; k < 4; ++k) {
            float v = vals[k];
#pragma unroll
            for (int off = 16; off; off >>= 1) v += __shfl_down_sync(0xffffffffu, v, off);
            if (lane == 0) rbuf[k][w] = v;
        }
        __syncthreads();
        if (tx == 0) {
#pragma unroll
            for (int k = 0; k < 4; ++k)
                g_part[blk][k] = rbuf[k][0] + rbuf[k][1] + rbuf[k][2] + rbuf[k][3] + rbuf[k][4];
        }
    }

    // ---------------- fused finalize: last block reduces all partials ----------------
    __shared__ int isLast;
    if (tx == 0) {
        __threadfence();
        unsigned t = atomicAdd(&g_ctr, 1u);
        isLast = (t == (unsigned)(NBLK - 1)) ? 1 : 0;
    }
    __syncthreads();

    if (isLast) {
        double a0 = 0.0, a1 = 0.0, a2 = 0.0, a3 = 0.0;
        const float4* gp = (const float4*)g_part;
        for (int idx = tx; idx < NBLK; idx += NTHR) {
            float4 v = __ldcg(&gp[idx]);
            a0 += (double)v.x; a1 += (double)v.y; a2 += (double)v.z; a3 += (double)v.w;
        }
#pragma unroll
        for (int off = 16; off; off >>= 1) {
            a0 += __shfl_down_sync(0xffffffffu, a0, off);
            a1 += __shfl_down_sync(0xffffffffu, a1, off);
            a2 += __shfl_down_sync(0xffffffffu, a2, off);
            a3 += __shfl_down_sync(0xffffffffu, a3, off);
        }
        __shared__ double sd[4][5];
        if (lane == 0) { sd[0][w] = a0; sd[1][w] = a1; sd[2][w] = a2; sd[3][w] = a3; }
        __syncthreads();
        if (tx == 0) {
            double t0 = 0, t1 = 0, t2 = 0, t3 = 0;
#pragma unroll
            for (int k = 0; k < 5; ++k) { t0 += sd[0][k]; t1 += sd[1][k]; t2 += sd[2][k]; t3 += sd[3][k]; }
            const double NI = 256.0 * 126.0 * 126.0;
            double loss_base = t0 / 300000.0;
            double loss_bc   = t1 / (256.0 * 988.0);
            double loss_cont = (t2 / NI) / 1e-5;
            double loss_ns   = (t3 / (NI * 2.0)) / 0.01;
            double A_LOSS = 1.0 - 0.3 - 0.3 - 0.3;
            out[0] = (float)(A_LOSS * loss_base + 0.3 * loss_cont + 0.3 * loss_ns + 0.3 * loss_bc);
            g_ctr = 0u;   // reset for graph replay
        }
    }
}

extern "C" void kernel_launch(void* const* d_in, const int* in_sizes, int n_in,
                              void* d_out, int out_size) {
    const int SMALL = 256 * 128 * 128;
    int idx_in = 0;
    for (int i = 0; i < n_in; ++i)
        if (in_sizes[i] == SMALL) { idx_in = i; break; }
    const float* inp = (const float*)d_in[idx_in];
    const float* big[2];
    int nb = 0;
    for (int i = 0; i < n_in && nb < 2; ++i)
        if (i != idx_in) big[nb++] = (const float*)d_in[i];
    const float* outp = big[0];
    const float* tgt  = big[1];

    physics_kernel<<<NBLK, NTHR>>>(inp, outp, tgt, (float*)d_out);
}

// round 6
// speedup vs baseline: 1.2085x; 1.1560x over previous
#include <cuda_runtime.h>

#define NBLK 1024   // 256 batches * 4 quarters
#define NTHR 64     // 2 warps; each warp = one 16-row chunk, full row width

__device__ float g_part[NBLK][4];
__device__ unsigned int g_ctr;

__global__ __launch_bounds__(NTHR, 8) void physics_kernel(
    const float* __restrict__ inp,   // (256,1,128,128)
    const float* __restrict__ outp,  // (256,3,128,128)
    const float* __restrict__ tgt,   // (256,3,128,128)
    float* __restrict__ out)
{
    const int blk  = blockIdx.x;
    const int b    = blk >> 2;
    const int q    = blk & 3;
    const int tx   = threadIdx.x;
    const int lane = tx & 31;
    const int w    = tx >> 5;

    constexpr float INV_SX  = 127.0f / 1.2f;
    constexpr float INV_2SX = 127.0f / 2.4f;
    constexpr float INV_SY  = 127.0f / 0.8f;
    constexpr float INV_2SY = 127.0f / 1.6f;
    constexpr float C2X = INV_2SX * INV_2SX;
    constexpr float C2Y = INV_2SY * INV_2SY;

    const float* Ob = outp + b * 49152;
    const float* Tb = tgt  + b * 49152;
    const float* Ib = inp  + b * 16384;

    float s_base = 0.f, s_bc = 0.f, s_cont = 0.f, s_ns = 0.f;

    // ---------------- base loss + boundary loss (float4 over 32 rows) ----------------
    {
        const float4* O4 = (const float4*)Ob;
        const float4* T4 = (const float4*)Tb;
#pragma unroll
        for (int it = 0; it < 16; ++it) {
            int idx4 = tx + it * NTHR;               // 0..1023
            int y    = q * 32 + (idx4 >> 5);
            int col4 = idx4 & 31;
            int idx  = y * 32 + col4;
            float4 o0 = O4[idx], o1 = O4[4096 + idx], o2 = O4[8192 + idx];
            float4 t0 = T4[idx], t1 = T4[4096 + idx], t2 = T4[8192 + idx];
            float d;
            d = o0.x - t0.x; s_base += d * d;  d = o0.y - t0.y; s_base += d * d;
            d = o0.z - t0.z; s_base += d * d;  d = o0.w - t0.w; s_base += d * d;
            d = o1.x - t1.x; s_base += d * d;  d = o1.y - t1.y; s_base += d * d;
            d = o1.z - t1.z; s_base += d * d;  d = o1.w - t1.w; s_base += d * d;
            d = o2.x - t2.x; s_base += d * d;  d = o2.y - t2.y; s_base += d * d;
            d = o2.z - t2.z; s_base += d * d;  d = o2.w - t2.w; s_base += d * d;

            bool midrow = (y >= 55) && (y < 73);
            if (y == 0 || y == 127)
                s_bc += o1.x * o1.x + o1.y * o1.y + o1.z * o1.z + o1.w * o1.w
                      + o2.x * o2.x + o2.y * o2.y + o2.z * o2.z + o2.w * o2.w;
            if (col4 == 0) {
                if (midrow) { float e = o1.x - 0.01f; s_bc += e * e; }
                else        s_bc += o1.x * o1.x + o2.x * o2.x;
            }
            if (col4 == 31) {
                if (midrow) s_bc += o0.w * o0.w;
                else        s_bc += o1.w * o1.w + o2.w * o2.w;
            }
        }
    }

    // ---------------- PDE on cropped 126x126 interior ----------------
    // Warp covers a full row: lane l owns global cols 4l..4l+3 = cropped c=4l-1..4l+2.
    // Element t: c = 4*lane - 1 + t. Invalid: lane0 t=0 (c=-1), lane31 t=3 (c=126).
    const int chunk = q * 2 + w;                 // 0..7
    const int y0  = chunk * 16;
    const int jlo = max(y0 - 1, 0);
    const int jhi = min(y0 + 15, 126);

    const float4* U4 = (const float4*)(Ob + 16384);
    const float4* V4 = (const float4*)(Ob + 32768);
    const float4* P4 = (const float4*)(Ob);
    const float4* A4 = (const float4*)(Ib);

#define ROWI(j) (((j) + 1) * 32 + lane)

    float um2[4], um1[4], uc[4], up1[4], up2[4];
    float vm2[4], vm1[4], vc[4], vp1[4], vp2[4];
    float pm1[4], pc[4], pp1[4];
#pragma unroll
    for (int t = 0; t < 4; ++t) {
        um2[t] = um1[t] = 0.f; vm2[t] = vm1[t] = 0.f; pm1[t] = 0.f;
    }

#define LD4(dst, arrptr, j) { float4 _t = (arrptr)[ROWI(j)]; \
        dst[0]=_t.x; dst[1]=_t.y; dst[2]=_t.z; dst[3]=_t.w; }

    if (jlo >= 2) { LD4(um2, U4, jlo - 2); LD4(vm2, V4, jlo - 2); }
    if (jlo >= 1) { LD4(um1, U4, jlo - 1); LD4(vm1, V4, jlo - 1); LD4(pm1, P4, jlo - 1); }
    LD4(uc,  U4, jlo);      LD4(vc,  V4, jlo);      LD4(pc,  P4, jlo);
    LD4(up1, U4, jlo + 1);  LD4(vp1, V4, jlo + 1);  LD4(pp1, P4, jlo + 1);
    LD4(up2, U4, jlo + 2);  LD4(vp2, V4, jlo + 2);

    float wt[4] = {1.f, 1.f, 1.f, 1.f};
    if (lane == 0)  wt[0] = 0.f;
    if (lane == 31) wt[3] = 0.f;

    for (int j = jlo; j < jhi; ++j) {
        // prefetch next rows (uniform predicates)
        float nu[4] = {0,0,0,0}, nv[4] = {0,0,0,0}, np[4] = {0,0,0,0}, al[4];
        if (j + 3 <= 125) { LD4(nu, U4, j + 3); LD4(nv, V4, j + 3); }
        if (j + 2 <= 125) { LD4(np, P4, j + 2); }
        LD4(al, A4, j);

        // x-halo shuffles (10 total)
        float upz = __shfl_up_sync(0xffffffffu, uc[2], 1);
        float upw = __shfl_up_sync(0xffffffffu, uc[3], 1);
        float unx = __shfl_down_sync(0xffffffffu, uc[0], 1);
        float uny = __shfl_down_sync(0xffffffffu, uc[1], 1);
        float vpz = __shfl_up_sync(0xffffffffu, vc[2], 1);
        float vpw = __shfl_up_sync(0xffffffffu, vc[3], 1);
        float vnx = __shfl_down_sync(0xffffffffu, vc[0], 1);
        float vny = __shfl_down_sync(0xffffffffu, vc[1], 1);
        float ppw = __shfl_up_sync(0xffffffffu, pc[3], 1);
        float pnx = __shfl_down_sync(0xffffffffu, pc[0], 1);

        // 8-element stencil windows; element t uses [t..t+4], center t+2
        float uw[8] = {upz, upw, uc[0], uc[1], uc[2], uc[3], unx, uny};
        float vw[8] = {vpz, vpw, vc[0], vc[1], vc[2], vc[3], vnx, vny};
        float pw[8] = {0.f, ppw, pc[0], pc[1], pc[2], pc[3], pnx, 0.f};

        float du_dx[4], du_dxx[4], dv_dx[4], dv_dxx[4], dp_dx[4];
#pragma unroll
        for (int t = 0; t < 4; ++t) {
            du_dx[t]  = (uw[t + 3] - uw[t + 1]) * INV_2SX;
            du_dxx[t] = (uw[t + 4] - 2.f * uw[t + 2] + uw[t]) * C2X;
            dv_dx[t]  = (vw[t + 3] - vw[t + 1]) * INV_2SX;
            dv_dxx[t] = (vw[t + 4] - 2.f * vw[t + 2] + vw[t]) * C2X;
            dp_dx[t]  = (pw[t + 3] - pw[t + 1]) * INV_2SX;
        }
        if (lane == 0) {
            // t=1: c=0 (cls0); t=2: c=1 (cls1)
            du_dx[1]  = (uw[4] - uw[3]) * INV_SX;
            du_dxx[1] = ((uw[5] - uw[3]) * INV_2SX - (uw[4] - uw[3]) * INV_SX) * INV_SX;
            du_dxx[2] = ((uw[6] - uw[4]) * INV_2SX - (uw[4] - uw[3]) * INV_SX) * INV_2SX;
            dv_dx[1]  = (vw[4] - vw[3]) * INV_SX;
            dv_dxx[1] = ((vw[5] - vw[3]) * INV_2SX - (vw[4] - vw[3]) * INV_SX) * INV_SX;
            dv_dxx[2] = ((vw[6] - vw[4]) * INV_2SX - (vw[4] - vw[3]) * INV_SX) * INV_2SX;
            dp_dx[1]  = (pw[4] - pw[3]) * INV_SX;
        }
        if (lane == 31) {
            // t=1: c=124 (cls3); t=2: c=125 (cls4)
            du_dxx[1] = ((uw[4] - uw[3]) * INV_SX - (uw[3] - uw[1]) * INV_2SX) * INV_2SX;
            du_dx[2]  = (uw[4] - uw[3]) * INV_SX;
            du_dxx[2] = ((uw[4] - uw[3]) * INV_SX - (uw[4] - uw[2]) * INV_2SX) * INV_SX;
            dv_dxx[1] = ((vw[4] - vw[3]) * INV_SX - (vw[3] - vw[1]) * INV_2SX) * INV_2SX;
            dv_dx[2]  = (vw[4] - vw[3]) * INV_SX;
            dv_dxx[2] = ((vw[4] - vw[3]) * INV_SX - (vw[4] - vw[2]) * INV_2SX) * INV_SX;
            dp_dx[2]  = (pw[4] - pw[3]) * INV_SX;
        }

        // y-direction (warp-uniform class)
        float du_dy[4], du_dyy[4], dv_dy[4], dv_dyy[4], dp_dy[4];
#pragma unroll
        for (int t = 0; t < 4; ++t) {
            du_dy[t]  = (up1[t] - um1[t]) * INV_2SY;
            du_dyy[t] = (up2[t] - 2.f * uc[t] + um2[t]) * C2Y;
            dv_dy[t]  = (vp1[t] - vm1[t]) * INV_2SY;
            dv_dyy[t] = (vp2[t] - 2.f * vc[t] + vm2[t]) * C2Y;
            dp_dy[t]  = (pp1[t] - pm1[t]) * INV_2SY;
        }
        if (j < 2 || j > 123) {
            if (j == 0) {
#pragma unroll
                for (int t = 0; t < 4; ++t) {
                    du_dy[t]  = (up1[t] - uc[t]) * INV_SY;
                    du_dyy[t] = ((up2[t] - uc[t]) * INV_2SY - (up1[t] - uc[t]) * INV_SY) * INV_SY;
                    dv_dy[t]  = (vp1[t] - vc[t]) * INV_SY;
                    dv_dyy[t] = ((vp2[t] - vc[t]) * INV_2SY - (vp1[t] - vc[t]) * INV_SY) * INV_SY;
                    dp_dy[t]  = (pp1[t] - pc[t]) * INV_SY;
                }
            } else if (j == 1) {
#pragma unroll
                for (int t = 0; t < 4; ++t) {
                    du_dyy[t] = ((up2[t] - uc[t]) * INV_2SY - (uc[t] - um1[t]) * INV_SY) * INV_2SY;
                    dv_dyy[t] = ((vp2[t] - vc[t]) * INV_2SY - (vc[t] - vm1[t]) * INV_SY) * INV_2SY;
                }
            } else if (j == 124) {
#pragma unroll
                for (int t = 0; t < 4; ++t) {
                    du_dyy[t] = ((up1[t] - uc[t]) * INV_SY - (uc[t] - um2[t]) * INV_2SY) * INV_2SY;
                    dv_dyy[t] = ((vp1[t] - vc[t]) * INV_SY - (vc[t] - vm2[t]) * INV_2SY) * INV_2SY;
                }
            } else { // j == 125
#pragma unroll
                for (int t = 0; t < 4; ++t) {
                    du_dy[t]  = (uc[t] - um1[t]) * INV_SY;
                    du_dyy[t] = ((uc[t] - um1[t]) * INV_SY - (uc[t] - um2[t]) * INV_2SY) * INV_SY;
                    dv_dy[t]  = (vc[t] - vm1[t]) * INV_SY;
                    dv_dyy[t] = ((vc[t] - vm1[t]) * INV_SY - (vc[t] - vm2[t]) * INV_2SY) * INV_SY;
                    dp_dy[t]  = (pc[t] - pm1[t]) * INV_SY;
                }
            }
        }

        // residuals
#pragma unroll
        for (int t = 0; t < 4; ++t) {
            float div = du_dx[t] + dv_dy[t];
            s_cont += wt[t] * div * div;
            float xr = uc[t] * du_dx[t] + vc[t] * du_dy[t] + dp_dx[t]
                     - (du_dxx[t] + du_dyy[t]) + al[t] * uc[t];
            float yr = uc[t] * dv_dx[t] + vc[t] * dv_dy[t] + dp_dy[t]
                     - (dv_dxx[t] + dv_dyy[t]) + al[t] * vc[t];
            s_ns += wt[t] * (xr * xr + yr * yr);
        }

        // rotate register windows
#pragma unroll
        for (int t = 0; t < 4; ++t) {
            um2[t] = um1[t]; um1[t] = uc[t]; uc[t] = up1[t]; up1[t] = up2[t]; up2[t] = nu[t];
            vm2[t] = vm1[t]; vm1[t] = vc[t]; vc[t] = vp1[t]; vp1[t] = vp2[t]; vp2[t] = nv[t];
            pm1[t] = pc[t];  pc[t] = pp1[t]; pp1[t] = np[t];
        }
    }

    // ---------------- block reduction -> g_part ----------------
    {
        float vals[4] = {s_base, s_bc, s_cont, s_ns};
        __shared__ float rbuf[4][2];
#pragma unroll
        for (int k = 0; k < 4; ++k) {
            float v = vals[k];
#pragma unroll
            for (int off = 16; off; off >>= 1) v += __shfl_down_sync(0xffffffffu, v, off);
            if (lane == 0) rbuf[k][w] = v;
        }
        __syncthreads();
        if (tx == 0) {
#pragma unroll
            for (int k = 0; k < 4; ++k)
                g_part[blk][k] = rbuf[k][0] + rbuf[k][1];
        }
    }

    // ---------------- fused finalize: last block reduces all partials ----------------
    __shared__ int isLast;
    if (tx == 0) {
        __threadfence();
        unsigned t = atomicAdd(&g_ctr, 1u);
        isLast = (t == (unsigned)(NBLK - 1)) ? 1 : 0;
    }
    __syncthreads();

    if (isLast) {
        double a0 = 0.0, a1 = 0.0, a2 = 0.0, a3 = 0.0;
        const float4* gp = (const float4*)g_part;
        for (int idx = tx; idx < NBLK; idx += NTHR) {
            float4 v = __ldcg(&gp[idx]);
            a0 += (double)v.x; a1 += (double)v.y; a2 += (double)v.z; a3 += (double)v.w;
        }
#pragma unroll
        for (int off = 16; off; off >>= 1) {
            a0 += __shfl_down_sync(0xffffffffu, a0, off);
            a1 += __shfl_down_sync(0xffffffffu, a1, off);
            a2 += __shfl_down_sync(0xffffffffu, a2, off);
            a3 += __shfl_down_sync(0xffffffffu, a3, off);
        }
        __shared__ double sd[4][2];
        if (lane == 0) { sd[0][w] = a0; sd[1][w] = a1; sd[2][w] = a2; sd[3][w] = a3; }
        __syncthreads();
        if (tx == 0) {
            double t0 = sd[0][0] + sd[0][1];
            double t1 = sd[1][0] + sd[1][1];
            double t2 = sd[2][0] + sd[2][1];
            double t3 = sd[3][0] + sd[3][1];
            const double NI = 256.0 * 126.0 * 126.0;
            double loss_base = t0 / 300000.0;
            double loss_bc   = t1 / (256.0 * 988.0);
            double loss_cont = (t2 / NI) / 1e-5;
            double loss_ns   = (t3 / (NI * 2.0)) / 0.01;
            double A_LOSS = 1.0 - 0.3 - 0.3 - 0.3;
            out[0] = (float)(A_LOSS * loss_base + 0.3 * loss_cont + 0.3 * loss_ns + 0.3 * loss_bc);
            g_ctr = 0u;   // reset for graph replay
        }
    }
}

extern "C" void kernel_launch(void* const* d_in, const int* in_sizes, int n_in,
                              void* d_out, int out_size) {
    const int SMALL = 256 * 128 * 128;
    int idx_in = 0;
    for (int i = 0; i < n_in; ++i)
        if (in_sizes[i] == SMALL) { idx_in = i; break; }
    const float* inp = (const float*)d_in[idx_in];
    const float* big[2];
    int nb = 0;
    for (int i = 0; i < n_in && nb < 2; ++i)
        if (i != idx_in) big[nb++] = (const float*)d_in[i];
    const float* outp = big[0];
    const float* tgt  = big[1];

    physics_kernel<<<NBLK, NTHR>>>(inp, outp, tgt, (float*)d_out);
}

// round 7
// speedup vs baseline: 1.2105x; 1.0016x over previous
#include <cuda_runtime.h>

#define NBLK 1024   // 256 batches * 4 quarters
#define NTHR 64     // 2 warps; each warp = one 16-row chunk, full row width

__device__ float g_part[NBLK][4];
__device__ unsigned int g_ctr;

__global__ __launch_bounds__(NTHR, 8) void physics_kernel(
    const float* __restrict__ inp,   // (256,1,128,128)
    const float* __restrict__ outp,  // (256,3,128,128)
    const float* __restrict__ tgt,   // (256,3,128,128)
    float* __restrict__ out)
{
    const int blk  = blockIdx.x;
    const int b    = blk >> 2;
    const int q    = blk & 3;
    const int tx   = threadIdx.x;
    const int lane = tx & 31;
    const int w    = tx >> 5;

    constexpr float INV_SX  = 127.0f / 1.2f;
    constexpr float INV_2SX = 127.0f / 2.4f;
    constexpr float INV_SY  = 127.0f / 0.8f;
    constexpr float INV_2SY = 127.0f / 1.6f;
    constexpr float C2X = INV_2SX * INV_2SX;
    constexpr float C2Y = INV_2SY * INV_2SY;

    const float* Ob = outp + b * 49152;
    const float* Tb = tgt  + b * 49152;
    const float* Ib = inp  + b * 16384;

    float s_base = 0.f, s_bc = 0.f, s_cont = 0.f, s_ns = 0.f;

    // ---------------- fused PDE + base/boundary loop ----------------
    // Warp covers a full row: lane l owns global cols 4l..4l+3 = cropped c=4l-1..4l+2.
    const int chunk = q * 2 + w;                 // 0..7
    const int y0  = chunk * 16;
    const int jlo = max(y0 - 1, 0);
    const int jhi = min(y0 + 15, 126);
    const int npde = jhi - jlo;                  // 15 or 16

    const float4* O4 = (const float4*)Ob;
    const float4* T4 = (const float4*)Tb;
    const float4* U4 = (const float4*)(Ob + 16384);
    const float4* V4 = (const float4*)(Ob + 32768);
    const float4* P4 = (const float4*)(Ob);
    const float4* A4 = (const float4*)(Ib);

#define ROWI(j) (((j) + 1) * 32 + lane)
#define LD4(dst, arrptr, j) { float4 _t = (arrptr)[ROWI(j)]; \
        dst[0]=_t.x; dst[1]=_t.y; dst[2]=_t.z; dst[3]=_t.w; }

    float um2[4], um1[4], uc[4], up1[4], up2[4];
    float vm2[4], vm1[4], vc[4], vp1[4], vp2[4];
    float pm1[4], pc[4], pp1[4];
#pragma unroll
    for (int t = 0; t < 4; ++t) {
        um2[t] = um1[t] = 0.f; vm2[t] = vm1[t] = 0.f; pm1[t] = 0.f;
    }

    if (jlo >= 2) { LD4(um2, U4, jlo - 2); LD4(vm2, V4, jlo - 2); }
    if (jlo >= 1) { LD4(um1, U4, jlo - 1); LD4(vm1, V4, jlo - 1); LD4(pm1, P4, jlo - 1); }
    LD4(uc,  U4, jlo);      LD4(vc,  V4, jlo);      LD4(pc,  P4, jlo);
    LD4(up1, U4, jlo + 1);  LD4(vp1, V4, jlo + 1);  LD4(pp1, P4, jlo + 1);
    LD4(up2, U4, jlo + 2);  LD4(vp2, V4, jlo + 2);

    float wt[4] = {1.f, 1.f, 1.f, 1.f};
    if (lane == 0)  wt[0] = 0.f;
    if (lane == 31) wt[3] = 0.f;

#pragma unroll 1
    for (int it = 0; it < 16; ++it) {
        const int j = jlo + it;
        const bool pde = (it < npde);

        // ---- issue ALL loads up front (10 independent LDG.128) ----
        float nu[4] = {0,0,0,0}, nv[4] = {0,0,0,0}, np[4] = {0,0,0,0}, al[4] = {0,0,0,0};
        if (pde) {
            if (j + 3 <= 125) { LD4(nu, U4, j + 3); LD4(nv, V4, j + 3); }
            if (j + 2 <= 125) { LD4(np, P4, j + 2); }
            LD4(al, A4, j);
        }
        const int yb   = y0 + it;                 // base row (always valid, 16/warp)
        const int bidx = yb * 32 + lane;
        float4 o0 = O4[bidx], o1 = O4[4096 + bidx], o2 = O4[8192 + bidx];
        float4 t0 = T4[bidx], t1 = T4[4096 + bidx], t2 = T4[8192 + bidx];

        // ---- base + boundary compute (short, consumes o/t) ----
        {
            float d;
            d = o0.x - t0.x; s_base += d * d;  d = o0.y - t0.y; s_base += d * d;
            d = o0.z - t0.z; s_base += d * d;  d = o0.w - t0.w; s_base += d * d;
            d = o1.x - t1.x; s_base += d * d;  d = o1.y - t1.y; s_base += d * d;
            d = o1.z - t1.z; s_base += d * d;  d = o1.w - t1.w; s_base += d * d;
            d = o2.x - t2.x; s_base += d * d;  d = o2.y - t2.y; s_base += d * d;
            d = o2.z - t2.z; s_base += d * d;  d = o2.w - t2.w; s_base += d * d;

            bool midrow = (yb >= 55) && (yb < 73);
            if (yb == 0 || yb == 127)
                s_bc += o1.x * o1.x + o1.y * o1.y + o1.z * o1.z + o1.w * o1.w
                      + o2.x * o2.x + o2.y * o2.y + o2.z * o2.z + o2.w * o2.w;
            if (lane == 0) {
                if (midrow) { float e = o1.x - 0.01f; s_bc += e * e; }
                else        s_bc += o1.x * o1.x + o2.x * o2.x;
            }
            if (lane == 31) {
                if (midrow) s_bc += o0.w * o0.w;
                else        s_bc += o1.w * o1.w + o2.w * o2.w;
            }
        }

        // ---- PDE compute ----
        if (pde) {
            // x-halo shuffles
            float upz = __shfl_up_sync(0xffffffffu, uc[2], 1);
            float upw = __shfl_up_sync(0xffffffffu, uc[3], 1);
            float unx = __shfl_down_sync(0xffffffffu, uc[0], 1);
            float uny = __shfl_down_sync(0xffffffffu, uc[1], 1);
            float vpz = __shfl_up_sync(0xffffffffu, vc[2], 1);
            float vpw = __shfl_up_sync(0xffffffffu, vc[3], 1);
            float vnx = __shfl_down_sync(0xffffffffu, vc[0], 1);
            float vny = __shfl_down_sync(0xffffffffu, vc[1], 1);
            float ppw = __shfl_up_sync(0xffffffffu, pc[3], 1);
            float pnx = __shfl_down_sync(0xffffffffu, pc[0], 1);

            float uw[8] = {upz, upw, uc[0], uc[1], uc[2], uc[3], unx, uny};
            float vw[8] = {vpz, vpw, vc[0], vc[1], vc[2], vc[3], vnx, vny};
            float pw[8] = {0.f, ppw, pc[0], pc[1], pc[2], pc[3], pnx, 0.f};

            float du_dx[4], du_dxx[4], dv_dx[4], dv_dxx[4], dp_dx[4];
#pragma unroll
            for (int t = 0; t < 4; ++t) {
                du_dx[t]  = (uw[t + 3] - uw[t + 1]) * INV_2SX;
                du_dxx[t] = (uw[t + 4] - 2.f * uw[t + 2] + uw[t]) * C2X;
                dv_dx[t]  = (vw[t + 3] - vw[t + 1]) * INV_2SX;
                dv_dxx[t] = (vw[t + 4] - 2.f * vw[t + 2] + vw[t]) * C2X;
                dp_dx[t]  = (pw[t + 3] - pw[t + 1]) * INV_2SX;
            }
            if (lane == 0) {
                du_dx[1]  = (uw[4] - uw[3]) * INV_SX;
                du_dxx[1] = ((uw[5] - uw[3]) * INV_2SX - (uw[4] - uw[3]) * INV_SX) * INV_SX;
                du_dxx[2] = ((uw[6] - uw[4]) * INV_2SX - (uw[4] - uw[3]) * INV_SX) * INV_2SX;
                dv_dx[1]  = (vw[4] - vw[3]) * INV_SX;
                dv_dxx[1] = ((vw[5] - vw[3]) * INV_2SX - (vw[4] - vw[3]) * INV_SX) * INV_SX;
                dv_dxx[2] = ((vw[6] - vw[4]) * INV_2SX - (vw[4] - vw[3]) * INV_SX) * INV_2SX;
                dp_dx[1]  = (pw[4] - pw[3]) * INV_SX;
            }
            if (lane == 31) {
                du_dxx[1] = ((uw[4] - uw[3]) * INV_SX - (uw[3] - uw[1]) * INV_2SX) * INV_2SX;
                du_dx[2]  = (uw[4] - uw[3]) * INV_SX;
                du_dxx[2] = ((uw[4] - uw[3]) * INV_SX - (uw[4] - uw[2]) * INV_2SX) * INV_SX;
                dv_dxx[1] = ((vw[4] - vw[3]) * INV_SX - (vw[3] - vw[1]) * INV_2SX) * INV_2SX;
                dv_dx[2]  = (vw[4] - vw[3]) * INV_SX;
                dv_dxx[2] = ((vw[4] - vw[3]) * INV_SX - (vw[4] - vw[2]) * INV_2SX) * INV_SX;
                dp_dx[2]  = (pw[4] - pw[3]) * INV_SX;
            }

            // y-direction (warp-uniform class)
            float du_dy[4], du_dyy[4], dv_dy[4], dv_dyy[4], dp_dy[4];
#pragma unroll
            for (int t = 0; t < 4; ++t) {
                du_dy[t]  = (up1[t] - um1[t]) * INV_2SY;
                du_dyy[t] = (up2[t] - 2.f * uc[t] + um2[t]) * C2Y;
                dv_dy[t]  = (vp1[t] - vm1[t]) * INV_2SY;
                dv_dyy[t] = (vp2[t] - 2.f * vc[t] + vm2[t]) * C2Y;
                dp_dy[t]  = (pp1[t] - pm1[t]) * INV_2SY;
            }
            if (j < 2 || j > 123) {
                if (j == 0) {
#pragma unroll
                    for (int t = 0; t < 4; ++t) {
                        du_dy[t]  = (up1[t] - uc[t]) * INV_SY;
                        du_dyy[t] = ((up2[t] - uc[t]) * INV_2SY - (up1[t] - uc[t]) * INV_SY) * INV_SY;
                        dv_dy[t]  = (vp1[t] - vc[t]) * INV_SY;
                        dv_dyy[t] = ((vp2[t] - vc[t]) * INV_2SY - (vp1[t] - vc[t]) * INV_SY) * INV_SY;
                        dp_dy[t]  = (pp1[t] - pc[t]) * INV_SY;
                    }
                } else if (j == 1) {
#pragma unroll
                    for (int t = 0; t < 4; ++t) {
                        du_dyy[t] = ((up2[t] - uc[t]) * INV_2SY - (uc[t] - um1[t]) * INV_SY) * INV_2SY;
                        dv_dyy[t] = ((vp2[t] - vc[t]) * INV_2SY - (vc[t] - vm1[t]) * INV_SY) * INV_2SY;
                    }
                } else if (j == 124) {
#pragma unroll
                    for (int t = 0; t < 4; ++t) {
                        du_dyy[t] = ((up1[t] - uc[t]) * INV_SY - (uc[t] - um2[t]) * INV_2SY) * INV_2SY;
                        dv_dyy[t] = ((vp1[t] - vc[t]) * INV_SY - (vc[t] - vm2[t]) * INV_2SY) * INV_2SY;
                    }
                } else { // j == 125
#pragma unroll
                    for (int t = 0; t < 4; ++t) {
                        du_dy[t]  = (uc[t] - um1[t]) * INV_SY;
                        du_dyy[t] = ((uc[t] - um1[t]) * INV_SY - (uc[t] - um2[t]) * INV_2SY) * INV_SY;
                        dv_dy[t]  = (vc[t] - vm1[t]) * INV_SY;
                        dv_dyy[t] = ((vc[t] - vm1[t]) * INV_SY - (vc[t] - vm2[t]) * INV_2SY) * INV_SY;
                        dp_dy[t]  = (pc[t] - pm1[t]) * INV_SY;
                    }
                }
            }

            // residuals
#pragma unroll
            for (int t = 0; t < 4; ++t) {
                float div = du_dx[t] + dv_dy[t];
                s_cont += wt[t] * div * div;
                float xr = uc[t] * du_dx[t] + vc[t] * du_dy[t] + dp_dx[t]
                         - (du_dxx[t] + du_dyy[t]) + al[t] * uc[t];
                float yr = uc[t] * dv_dx[t] + vc[t] * dv_dy[t] + dp_dy[t]
                         - (dv_dxx[t] + dv_dyy[t]) + al[t] * vc[t];
                s_ns += wt[t] * (xr * xr + yr * yr);
            }

            // rotate register windows
#pragma unroll
            for (int t = 0; t < 4; ++t) {
                um2[t] = um1[t]; um1[t] = uc[t]; uc[t] = up1[t]; up1[t] = up2[t]; up2[t] = nu[t];
                vm2[t] = vm1[t]; vm1[t] = vc[t]; vc[t] = vp1[t]; vp1[t] = vp2[t]; vp2[t] = nv[t];
                pm1[t] = pc[t];  pc[t] = pp1[t]; pp1[t] = np[t];
            }
        }
    }

    // ---------------- block reduction -> g_part ----------------
    {
        float vals[4] = {s_base, s_bc, s_cont, s_ns};
        __shared__ float rbuf[4][2];
#pragma unroll
        for (int k = 0; k < 4; ++k) {
            float v = vals[k];
#pragma unroll
            for (int off = 16; off; off >>= 1) v += __shfl_down_sync(0xffffffffu, v, off);
            if (lane == 0) rbuf[k][w] = v;
        }
        __syncthreads();
        if (tx == 0) {
#pragma unroll
            for (int k = 0; k < 4; ++k)
                g_part[blk][k] = rbuf[k][0] + rbuf[k][1];
        }
    }

    // ---------------- fused finalize: last block reduces all partials ----------------
    __shared__ int isLast;
    if (tx == 0) {
        __threadfence();
        unsigned t = atomicAdd(&g_ctr, 1u);
        isLast = (t == (unsigned)(NBLK - 1)) ? 1 : 0;
    }
    __syncthreads();

    if (isLast) {
        double a0 = 0.0, a1 = 0.0, a2 = 0.0, a3 = 0.0;
        const float4* gp = (const float4*)g_part;
        for (int idx = tx; idx < NBLK; idx += NTHR) {
            float4 v = __ldcg(&gp[idx]);
            a0 += (double)v.x; a1 += (double)v.y; a2 += (double)v.z; a3 += (double)v.w;
        }
#pragma unroll
        for (int off = 16; off; off >>= 1) {
            a0 += __shfl_down_sync(0xffffffffu, a0, off);
            a1 += __shfl_down_sync(0xffffffffu, a1, off);
            a2 += __shfl_down_sync(0xffffffffu, a2, off);
            a3 += __shfl_down_sync(0xffffffffu, a3, off);
        }
        __shared__ double sd[4][2];
        if (lane == 0) { sd[0][w] = a0; sd[1][w] = a1; sd[2][w] = a2; sd[3][w] = a3; }
        __syncthreads();
        if (tx == 0) {
            double t0 = sd[0][0] + sd[0][1];
            double t1 = sd[1][0] + sd[1][1];
            double t2 = sd[2][0] + sd[2][1];
            double t3 = sd[3][0] + sd[3][1];
            const double NI = 256.0 * 126.0 * 126.0;
            double loss_base = t0 / 300000.0;
            double loss_bc   = t1 / (256.0 * 988.0);
            double loss_cont = (t2 / NI) / 1e-5;
            double loss_ns   = (t3 / (NI * 2.0)) / 0.01;
            double A_LOSS = 1.0 - 0.3 - 0.3 - 0.3;
            out[0] = (float)(A_LOSS * loss_base + 0.3 * loss_cont + 0.3 * loss_ns + 0.3 * loss_bc);
            g_ctr = 0u;   // reset for graph replay
        }
    }
}

extern "C" void kernel_launch(void* const* d_in, const int* in_sizes, int n_in,
                              void* d_out, int out_size) {
    const int SMALL = 256 * 128 * 128;
    int idx_in = 0;
    for (int i = 0; i < n_in; ++i)
        if (in_sizes[i] == SMALL) { idx_in = i; break; }
    const float* inp = (const float*)d_in[idx_in];
    const float* big[2];
    int nb = 0;
    for (int i = 0; i < n_in && nb < 2; ++i)
        if (i != idx_in) big[nb++] = (const float*)d_in[i];
    const float* outp = big[0];
    const float* tgt  = big[1];

    physics_kernel<<<NBLK, NTHR>>>(inp, outp, tgt, (float*)d_out);
}

// round 8
// speedup vs baseline: 1.2767x; 1.0546x over previous
#include <cuda_runtime.h>

#define NBLK 1024   // 256 batches * 4 quarters
#define NTHR 64     // 2 warps; each warp = one 16-row chunk, full row width

__device__ float g_part[NBLK][4];
__device__ unsigned int g_ctr;

__global__ __launch_bounds__(NTHR, 8) void physics_kernel(
    const float* __restrict__ inp,   // (256,1,128,128)
    const float* __restrict__ outp,  // (256,3,128,128)
    const float* __restrict__ tgt,   // (256,3,128,128)
    float* __restrict__ out)
{
    const int blk  = blockIdx.x;
    const int b    = blk >> 2;
    const int q    = blk & 3;
    const int tx   = threadIdx.x;
    const int lane = tx & 31;
    const int w    = tx >> 5;

    constexpr float INV_SX  = 127.0f / 1.2f;
    constexpr float INV_2SX = 127.0f / 2.4f;
    constexpr float INV_SY  = 127.0f / 0.8f;
    constexpr float INV_2SY = 127.0f / 1.6f;
    constexpr float C2X = INV_2SX * INV_2SX;
    constexpr float C2Y = INV_2SY * INV_2SY;

    const float* Ob = outp + b * 49152;
    const float* Tb = tgt  + b * 49152;
    const float* Ib = inp  + b * 16384;

    // split accumulators to break FMA dependency chains
    float sb0 = 0.f, sb1 = 0.f, sb2 = 0.f, sb3 = 0.f;   // base, per component
    float sc0 = 0.f, sc1 = 0.f;                          // cont
    float sn0 = 0.f, sn1 = 0.f;                          // ns
    float s_bc = 0.f;

    // ---------------- fused PDE + base/boundary loop ----------------
    const int chunk = q * 2 + w;                 // 0..7
    const int y0  = chunk * 16;
    const int jlo = max(y0 - 1, 0);
    const int jhi = min(y0 + 15, 126);
    const int npde = jhi - jlo;                  // 15 or 16

    const float4* O4 = (const float4*)Ob;
    const float4* T4 = (const float4*)Tb;
    const float4* U4 = (const float4*)(Ob + 16384);
    const float4* V4 = (const float4*)(Ob + 32768);
    const float4* P4 = (const float4*)(Ob);
    const float4* A4 = (const float4*)(Ib);

#define ROWI(j) (((j) + 1) * 32 + lane)
#define LD4(dst, arrptr, j) { float4 _t = (arrptr)[ROWI(j)]; \
        dst[0]=_t.x; dst[1]=_t.y; dst[2]=_t.z; dst[3]=_t.w; }
#define LD4S(dst, arrptr, j) { float4 _t = __ldcs(&(arrptr)[ROWI(j)]); \
        dst[0]=_t.x; dst[1]=_t.y; dst[2]=_t.z; dst[3]=_t.w; }

    float um2[4], um1[4], uc[4], up1[4], up2[4];
    float vm2[4], vm1[4], vc[4], vp1[4], vp2[4];
    float pm1[4], pc[4], pp1[4];
#pragma unroll
    for (int t = 0; t < 4; ++t) {
        um2[t] = um1[t] = 0.f; vm2[t] = vm1[t] = 0.f; pm1[t] = 0.f;
    }

    if (jlo >= 2) { LD4(um2, U4, jlo - 2); LD4(vm2, V4, jlo - 2); }
    if (jlo >= 1) { LD4(um1, U4, jlo - 1); LD4(vm1, V4, jlo - 1); LD4(pm1, P4, jlo - 1); }
    LD4(uc,  U4, jlo);      LD4(vc,  V4, jlo);      LD4(pc,  P4, jlo);
    LD4(up1, U4, jlo + 1);  LD4(vp1, V4, jlo + 1);  LD4(pp1, P4, jlo + 1);
    LD4(up2, U4, jlo + 2);  LD4(vp2, V4, jlo + 2);

    float wt[4] = {1.f, 1.f, 1.f, 1.f};
    if (lane == 0)  wt[0] = 0.f;
    if (lane == 31) wt[3] = 0.f;

#pragma unroll 2
    for (int it = 0; it < 16; ++it) {
        const int j = jlo + it;
        const bool pde = (it < npde);

        // ---- issue ALL loads up front ----
        float nu[4] = {0,0,0,0}, nv[4] = {0,0,0,0}, np[4] = {0,0,0,0}, al[4] = {0,0,0,0};
        if (pde) {
            if (j + 3 <= 125) { LD4(nu, U4, j + 3); LD4(nv, V4, j + 3); }
            if (j + 2 <= 125) { LD4(np, P4, j + 2); }
            LD4S(al, A4, j);
        }
        const int yb   = y0 + it;                 // base row (always valid, 16/warp)
        const int bidx = yb * 32 + lane;
        float4 o0 = O4[bidx], o1 = O4[4096 + bidx], o2 = O4[8192 + bidx];
        float4 t0 = __ldcs(&T4[bidx]);
        float4 t1 = __ldcs(&T4[4096 + bidx]);
        float4 t2 = __ldcs(&T4[8192 + bidx]);

        // ---- base + boundary compute (4 independent accumulator chains) ----
        {
            float d;
            d = o0.x - t0.x; sb0 += d * d;  d = o0.y - t0.y; sb1 += d * d;
            d = o0.z - t0.z; sb2 += d * d;  d = o0.w - t0.w; sb3 += d * d;
            d = o1.x - t1.x; sb0 += d * d;  d = o1.y - t1.y; sb1 += d * d;
            d = o1.z - t1.z; sb2 += d * d;  d = o1.w - t1.w; sb3 += d * d;
            d = o2.x - t2.x; sb0 += d * d;  d = o2.y - t2.y; sb1 += d * d;
            d = o2.z - t2.z; sb2 += d * d;  d = o2.w - t2.w; sb3 += d * d;

            bool midrow = (yb >= 55) && (yb < 73);
            if (yb == 0 || yb == 127)
                s_bc += o1.x * o1.x + o1.y * o1.y + o1.z * o1.z + o1.w * o1.w
                      + o2.x * o2.x + o2.y * o2.y + o2.z * o2.z + o2.w * o2.w;
            if (lane == 0) {
                if (midrow) { float e = o1.x - 0.01f; s_bc += e * e; }
                else        s_bc += o1.x * o1.x + o2.x * o2.x;
            }
            if (lane == 31) {
                if (midrow) s_bc += o0.w * o0.w;
                else        s_bc += o1.w * o1.w + o2.w * o2.w;
            }
        }

        // ---- PDE compute ----
        if (pde) {
            // x-halo shuffles
            float upz = __shfl_up_sync(0xffffffffu, uc[2], 1);
            float upw = __shfl_up_sync(0xffffffffu, uc[3], 1);
            float unx = __shfl_down_sync(0xffffffffu, uc[0], 1);
            float uny = __shfl_down_sync(0xffffffffu, uc[1], 1);
            float vpz = __shfl_up_sync(0xffffffffu, vc[2], 1);
            float vpw = __shfl_up_sync(0xffffffffu, vc[3], 1);
            float vnx = __shfl_down_sync(0xffffffffu, vc[0], 1);
            float vny = __shfl_down_sync(0xffffffffu, vc[1], 1);
            float ppw = __shfl_up_sync(0xffffffffu, pc[3], 1);
            float pnx = __shfl_down_sync(0xffffffffu, pc[0], 1);

            float uw[8] = {upz, upw, uc[0], uc[1], uc[2], uc[3], unx, uny};
            float vw[8] = {vpz, vpw, vc[0], vc[1], vc[2], vc[3], vnx, vny};
            float pw[8] = {0.f, ppw, pc[0], pc[1], pc[2], pc[3], pnx, 0.f};

            float du_dx[4], du_dxx[4], dv_dx[4], dv_dxx[4], dp_dx[4];
#pragma unroll
            for (int t = 0; t < 4; ++t) {
                du_dx[t]  = (uw[t + 3] - uw[t + 1]) * INV_2SX;
                du_dxx[t] = (uw[t + 4] - 2.f * uw[t + 2] + uw[t]) * C2X;
                dv_dx[t]  = (vw[t + 3] - vw[t + 1]) * INV_2SX;
                dv_dxx[t] = (vw[t + 4] - 2.f * vw[t + 2] + vw[t]) * C2X;
                dp_dx[t]  = (pw[t + 3] - pw[t + 1]) * INV_2SX;
            }
            if (lane == 0) {
                du_dx[1]  = (uw[4] - uw[3]) * INV_SX;
                du_dxx[1] = ((uw[5] - uw[3]) * INV_2SX - (uw[4] - uw[3]) * INV_SX) * INV_SX;
                du_dxx[2] = ((uw[6] - uw[4]) * INV_2SX - (uw[4] - uw[3]) * INV_SX) * INV_2SX;
                dv_dx[1]  = (vw[4] - vw[3]) * INV_SX;
                dv_dxx[1] = ((vw[5] - vw[3]) * INV_2SX - (vw[4] - vw[3]) * INV_SX) * INV_SX;
                dv_dxx[2] = ((vw[6] - vw[4]) * INV_2SX - (vw[4] - vw[3]) * INV_SX) * INV_2SX;
                dp_dx[1]  = (pw[4] - pw[3]) * INV_SX;
            }
            if (lane == 31) {
                du_dxx[1] = ((uw[4] - uw[3]) * INV_SX - (uw[3] - uw[1]) * INV_2SX) * INV_2SX;
                du_dx[2]  = (uw[4] - uw[3]) * INV_SX;
                du_dxx[2] = ((uw[4] - uw[3]) * INV_SX - (uw[4] - uw[2]) * INV_2SX) * INV_SX;
                dv_dxx[1] = ((vw[4] - vw[3]) * INV_SX - (vw[3] - vw[1]) * INV_2SX) * INV_2SX;
                dv_dx[2]  = (vw[4] - vw[3]) * INV_SX;
                dv_dxx[2] = ((vw[4] - vw[3]) * INV_SX - (vw[4] - vw[2]) * INV_2SX) * INV_SX;
                dp_dx[2]  = (pw[4] - pw[3]) * INV_SX;
            }

            // y-direction (warp-uniform class)
            float du_dy[4], du_dyy[4], dv_dy[4], dv_dyy[4], dp_dy[4];
#pragma unroll
            for (int t = 0; t < 4; ++t) {
                du_dy[t]  = (up1[t] - um1[t]) * INV_2SY;
                du_dyy[t] = (up2[t] - 2.f * uc[t] + um2[t]) * C2Y;
                dv_dy[t]  = (vp1[t] - vm1[t]) * INV_2SY;
                dv_dyy[t] = (vp2[t] - 2.f * vc[t] + vm2[t]) * C2Y;
                dp_dy[t]  = (pp1[t] - pm1[t]) * INV_2SY;
            }
            if (j < 2 || j > 123) {
                if (j == 0) {
#pragma unroll
                    for (int t = 0; t < 4; ++t) {
                        du_dy[t]  = (up1[t] - uc[t]) * INV_SY;
                        du_dyy[t] = ((up2[t] - uc[t]) * INV_2SY - (up1[t] - uc[t]) * INV_SY) * INV_SY;
                        dv_dy[t]  = (vp1[t] - vc[t]) * INV_SY;
                        dv_dyy[t] = ((vp2[t] - vc[t]) * INV_2SY - (vp1[t] - vc[t]) * INV_SY) * INV_SY;
                        dp_dy[t]  = (pp1[t] - pc[t]) * INV_SY;
                    }
                } else if (j == 1) {
#pragma unroll
                    for (int t = 0; t < 4; ++t) {
                        du_dyy[t] = ((up2[t] - uc[t]) * INV_2SY - (uc[t] - um1[t]) * INV_SY) * INV_2SY;
                        dv_dyy[t] = ((vp2[t] - vc[t]) * INV_2SY - (vc[t] - vm1[t]) * INV_SY) * INV_2SY;
                    }
                } else if (j == 124) {
#pragma unroll
                    for (int t = 0; t < 4; ++t) {
                        du_dyy[t] = ((up1[t] - uc[t]) * INV_SY - (uc[t] - um2[t]) * INV_2SY) * INV_2SY;
                        dv_dyy[t] = ((vp1[t] - vc[t]) * INV_SY - (vc[t] - vm2[t]) * INV_2SY) * INV_2SY;
                    }
                } else { // j == 125
#pragma unroll
                    for (int t = 0; t < 4; ++t) {
                        du_dy[t]  = (uc[t] - um1[t]) * INV_SY;
                        du_dyy[t] = ((uc[t] - um1[t]) * INV_SY - (uc[t] - um2[t]) * INV_2SY) * INV_SY;
                        dv_dy[t]  = (vc[t] - vm1[t]) * INV_SY;
                        dv_dyy[t] = ((vc[t] - vm1[t]) * INV_SY - (vc[t] - vm2[t]) * INV_2SY) * INV_SY;
                        dp_dy[t]  = (pc[t] - pm1[t]) * INV_SY;
                    }
                }
            }

            // residuals: 2 independent accumulator chains each
#pragma unroll
            for (int t = 0; t < 4; ++t) {
                float div = du_dx[t] + dv_dy[t];
                float cadd = wt[t] * div * div;
                if (t & 1) sc1 += cadd; else sc0 += cadd;
                float xr = uc[t] * du_dx[t] + vc[t] * du_dy[t] + dp_dx[t]
                         - (du_dxx[t] + du_dyy[t]) + al[t] * uc[t];
                float yr = uc[t] * dv_dx[t] + vc[t] * dv_dy[t] + dp_dy[t]
                         - (dv_dxx[t] + dv_dyy[t]) + al[t] * vc[t];
                float nadd = wt[t] * (xr * xr + yr * yr);
                if (t & 1) sn1 += nadd; else sn0 += nadd;
            }

            // rotate register windows
#pragma unroll
            for (int t = 0; t < 4; ++t) {
                um2[t] = um1[t]; um1[t] = uc[t]; uc[t] = up1[t]; up1[t] = up2[t]; up2[t] = nu[t];
                vm2[t] = vm1[t]; vm1[t] = vc[t]; vc[t] = vp1[t]; vp1[t] = vp2[t]; vp2[t] = nv[t];
                pm1[t] = pc[t];  pc[t] = pp1[t]; pp1[t] = np[t];
            }
        }
    }

    float s_base = (sb0 + sb1) + (sb2 + sb3);
    float s_cont = sc0 + sc1;
    float s_ns   = sn0 + sn1;

    // ---------------- block reduction -> g_part ----------------
    {
        float vals[4] = {s_base, s_bc, s_cont, s_ns};
        __shared__ float rbuf[4][2];
#pragma unroll
        for (int k = 0; k < 4; ++k) {
            float v = vals[k];
#pragma unroll
            for (int off = 16; off; off >>= 1) v += __shfl_down_sync(0xffffffffu, v, off);
            if (lane == 0) rbuf[k][w] = v;
        }
        __syncthreads();
        if (tx == 0) {
#pragma unroll
            for (int k = 0; k < 4; ++k)
                g_part[blk][k] = rbuf[k][0] + rbuf[k][1];
        }
    }

    // ---------------- fused finalize: last block reduces all partials ----------------
    __shared__ int isLast;
    if (tx == 0) {
        __threadfence();
        unsigned t = atomicAdd(&g_ctr, 1u);
        isLast = (t == (unsigned)(NBLK - 1)) ? 1 : 0;
    }
    __syncthreads();

    if (isLast) {
        double a0 = 0.0, a1 = 0.0, a2 = 0.0, a3 = 0.0;
        const float4* gp = (const float4*)g_part;
        for (int idx = tx; idx < NBLK; idx += NTHR) {
            float4 v = __ldcg(&gp[idx]);
            a0 += (double)v.x; a1 += (double)v.y; a2 += (double)v.z; a3 += (double)v.w;
        }
#pragma unroll
        for (int off = 16; off; off >>= 1) {
            a0 += __shfl_down_sync(0xffffffffu, a0, off);
            a1 += __shfl_down_sync(0xffffffffu, a1, off);
            a2 += __shfl_down_sync(0xffffffffu, a2, off);
            a3 += __shfl_down_sync(0xffffffffu, a3, off);
        }
        __shared__ double sd[4][2];
        if (lane == 0) { sd[0][w] = a0; sd[1][w] = a1; sd[2][w] = a2; sd[3][w] = a3; }
        __syncthreads();
        if (tx == 0) {
            double t0 = sd[0][0] + sd[0][1];
            double t1 = sd[1][0] + sd[1][1];
            double t2 = sd[2][0] + sd[2][1];
            double t3 = sd[3][0] + sd[3][1];
            const double NI = 256.0 * 126.0 * 126.0;
            double loss_base = t0 / 300000.0;
            double loss_bc   = t1 / (256.0 * 988.0);
            double loss_cont = (t2 / NI) / 1e-5;
            double loss_ns   = (t3 / (NI * 2.0)) / 0.01;
            double A_LOSS = 1.0 - 0.3 - 0.3 - 0.3;
            out[0] = (float)(A_LOSS * loss_base + 0.3 * loss_cont + 0.3 * loss_ns + 0.3 * loss_bc);
            g_ctr = 0u;   // reset for graph replay
        }
    }
}

extern "C" void kernel_launch(void* const* d_in, const int* in_sizes, int n_in,
                              void* d_out, int out_size) {
    const int SMALL = 256 * 128 * 128;
    int idx_in = 0;
    for (int i = 0; i < n_in; ++i)
        if (in_sizes[i] == SMALL) { idx_in = i; break; }
    const float* inp = (const float*)d_in[idx_in];
    const float* big[2];
    int nb = 0;
    for (int i = 0; i < n_in && nb < 2; ++i)
        if (i != idx_in) big[nb++] = (const float*)d_in[i];
    const float* outp = big[0];
    const float* tgt  = big[1];

    physics_kernel<<<NBLK, NTHR>>>(inp, outp, tgt, (float*)d_out);
}